// round 7
// baseline (speedup 1.0000x reference)
#include <cuda_runtime.h>

#define NV_MAX 50000
#define HDIM 64

// -------- scratch (no allocs allowed) --------
__device__ float g_A[NV_MAX * HDIM];      // x@W0 + pe@W1   (msg, send side)
__device__ float g_B[NV_MAX * HDIM];      // x@W2 + pe@W3   (msg, recv side)
__device__ float g_P[NV_MAX * HDIM];      // pe@V0          (pos, send side)
__device__ float g_Q[NV_MAX * HDIM];      // pe@V1          (pos, recv side)
__device__ float g_aggr[NV_MAX * HDIM];
__device__ float g_aggrp[NV_MAX * HDIM];

typedef unsigned long long ull_t;

__device__ __forceinline__ ull_t pack2(float lo, float hi) {
    ull_t r; asm("mov.b64 %0, {%1, %2};" : "=l"(r) : "f"(lo), "f"(hi)); return r;
}
__device__ __forceinline__ void unpack2(ull_t v, float& lo, float& hi) {
    asm("mov.b64 {%0, %1}, %2;" : "=f"(lo), "=f"(hi) : "l"(v));
}
__device__ __forceinline__ ull_t ffma2(ull_t a, ull_t b, ull_t c) {
    ull_t d; asm("fma.rn.f32x2 %0, %1, %2, %3;" : "=l"(d) : "l"(a), "l"(b), "l"(c)); return d;
}
__device__ __forceinline__ float tanh_f(float x) {
    float y; asm("tanh.approx.f32 %0, %1;" : "=f"(y) : "f"(x)); return y;
}
__device__ __forceinline__ float silu_f(float x) {
    // x * sigmoid(x) = 0.5*x*(1 + tanh(x/2))  -> single MUFU
    return 0.5f * x * (1.0f + tanh_f(0.5f * x));
}

// ------------------------------------------------------------
// Core microkernel: 8 rows x 4 cols per thread, software-pipelined.
//   inT: [K][ISTRIDE] transposed activations, pre-offset by row base r0
//   W  : [K][WSTRIDE] weights, pre-offset by col base c0
// ------------------------------------------------------------
template <int K, int ISTRIDE, int WSTRIDE>
__device__ __forceinline__ void gemm_8x4(
    const float* __restrict__ inT, const float* __restrict__ W, ull_t acc[8][2])
{
    float4 ha = *(const float4*)(inT);
    float4 hb = *(const float4*)(inT + 4);
    ulonglong2 w = *(const ulonglong2*)(W);
    #pragma unroll 8
    for (int k = 0; k < K; k++) {
        float4 nha, nhb; ulonglong2 nw;
        if (k + 1 < K) {
            nha = *(const float4*)(inT + (k + 1) * ISTRIDE);
            nhb = *(const float4*)(inT + (k + 1) * ISTRIDE + 4);
            nw  = *(const ulonglong2*)(W + (k + 1) * WSTRIDE);
        }
        ull_t p0 = pack2(ha.x, ha.x), p1 = pack2(ha.y, ha.y);
        ull_t p2 = pack2(ha.z, ha.z), p3 = pack2(ha.w, ha.w);
        ull_t p4 = pack2(hb.x, hb.x), p5 = pack2(hb.y, hb.y);
        ull_t p6 = pack2(hb.z, hb.z), p7 = pack2(hb.w, hb.w);
        acc[0][0] = ffma2(p0, w.x, acc[0][0]); acc[0][1] = ffma2(p0, w.y, acc[0][1]);
        acc[1][0] = ffma2(p1, w.x, acc[1][0]); acc[1][1] = ffma2(p1, w.y, acc[1][1]);
        acc[2][0] = ffma2(p2, w.x, acc[2][0]); acc[2][1] = ffma2(p2, w.y, acc[2][1]);
        acc[3][0] = ffma2(p3, w.x, acc[3][0]); acc[3][1] = ffma2(p3, w.y, acc[3][1]);
        acc[4][0] = ffma2(p4, w.x, acc[4][0]); acc[4][1] = ffma2(p4, w.y, acc[4][1]);
        acc[5][0] = ffma2(p5, w.x, acc[5][0]); acc[5][1] = ffma2(p5, w.y, acc[5][1]);
        acc[6][0] = ffma2(p6, w.x, acc[6][0]); acc[6][1] = ffma2(p6, w.y, acc[6][1]);
        acc[7][0] = ffma2(p7, w.x, acc[7][0]); acc[7][1] = ffma2(p7, w.y, acc[7][1]);
        ha = nha; hb = nhb; w = nw;
    }
}

__device__ __forceinline__ void zero_acc(ull_t acc[8][2]) {
    #pragma unroll
    for (int i = 0; i < 8; i++) { acc[i][0] = 0ULL; acc[i][1] = 0ULL; }
}

// ============================================================
// Kernel 1a: pre_AB — A,B projections (+ zero aggr buffers)
//   64 nodes/CTA; K=128 ([x;pe]) streamed in 2 chunks; 128 out cols.
// ============================================================
__global__ void __launch_bounds__(256, 3) pre_AB_kernel(
    const float* __restrict__ x, const float* __restrict__ pe,
    const float* __restrict__ msg_w1, const float* __restrict__ msg_b1,
    int N)
{
    extern __shared__ float sm[];
    float* sh_inT = sm;                   // [64][68]
    float* sh_Wc  = sh_inT + 64 * 68;     // [64][128]
    float* sh_b   = sh_Wc + 64 * 128;     // [128]

    int tid = threadIdx.x;
    int nb = blockIdx.x * 64;
    if (tid < 128) sh_b[tid] = (tid < 64) ? msg_b1[tid] : 0.0f;

    // zero aggregation buffers for this CTA's nodes (before edge kernel)
    for (int idx = tid; idx < 2048; idx += 256) {
        int n = idx & 63, s = (idx >> 6) & 15, which = idx >> 10;
        int gn = nb + n;
        if (gn < N) {
            float4* dst = (float4*)((which ? g_aggrp : g_aggr) + (size_t)gn * 64) + s;
            *dst = make_float4(0.f, 0.f, 0.f, 0.f);
        }
    }

    int tr = tid & 7, tc = tid >> 3;      // 8 groups x 32 groups
    int r0 = 8 * tr, c0 = 4 * tc;

    ull_t acc[8][2];
    zero_acc(acc);

    #pragma unroll 1
    for (int ch = 0; ch < 2; ch++) {
        __syncthreads();
        // weights chunk: A cols <- msg_w1 rows [ch*64, ch*64+64); B cols <- rows [128+ch*64, ...)
        for (int idx = tid; idx < 64 * 128; idx += 256) {
            int k = idx >> 7, c = idx & 127;
            sh_Wc[idx] = (c < 64) ? msg_w1[(ch * 64 + k) * 64 + c]
                                  : msg_w1[(128 + ch * 64 + k) * 64 + (c - 64)];
        }
        // input chunk (transposed): ch0 = x, ch1 = pe
        const float* src = (ch == 0) ? x : pe;
        for (int idx = tid; idx < 16 * 64; idx += 256) {
            int n = idx & 63, k4 = idx >> 6;
            int gn = nb + n;
            float4 v = make_float4(0.f, 0.f, 0.f, 0.f);
            if (gn < N) v = *(const float4*)(src + (size_t)gn * 64 + 4 * k4);
            sh_inT[(4 * k4 + 0) * 68 + n] = v.x;
            sh_inT[(4 * k4 + 1) * 68 + n] = v.y;
            sh_inT[(4 * k4 + 2) * 68 + n] = v.z;
            sh_inT[(4 * k4 + 3) * 68 + n] = v.w;
        }
        __syncthreads();
        gemm_8x4<64, 68, 128>(sh_inT + r0, sh_Wc + c0, acc);
    }

    float* dst = (c0 < 64) ? g_A : g_B;
    int lc = c0 & 63;
    float b0 = sh_b[c0], b1 = sh_b[c0 + 1], b2 = sh_b[c0 + 2], b3 = sh_b[c0 + 3];
    #pragma unroll
    for (int i = 0; i < 8; i++) {
        int gn = nb + r0 + i;
        if (gn < N) {
            float o0, o1, o2, o3;
            unpack2(acc[i][0], o0, o1);
            unpack2(acc[i][1], o2, o3);
            *(float4*)(dst + (size_t)gn * 64 + lc) =
                make_float4(o0 + b0, o1 + b1, o2 + b2, o3 + b3);
        }
    }
}

// ============================================================
// Kernel 1b: pre_PQ — P,Q projections; 64 nodes/CTA, K=64 (pe)
// ============================================================
__global__ void __launch_bounds__(256, 3) pre_PQ_kernel(
    const float* __restrict__ pe,
    const float* __restrict__ mpos_w1, const float* __restrict__ mpos_b1,
    int N)
{
    extern __shared__ float sm[];
    float* sh_inT = sm;                   // [64][68]
    float* sh_W   = sh_inT + 64 * 68;     // [64][128]
    float* sh_b   = sh_W + 64 * 128;      // [128]

    int tid = threadIdx.x;
    int nb = blockIdx.x * 64;
    if (tid < 128) sh_b[tid] = (tid < 64) ? mpos_b1[tid] : 0.0f;

    for (int idx = tid; idx < 64 * 128; idx += 256) {
        int k = idx >> 7, c = idx & 127;
        sh_W[idx] = (c < 64) ? mpos_w1[k * 64 + c]
                             : mpos_w1[(64 + k) * 64 + (c - 64)];
    }
    for (int idx = tid; idx < 16 * 64; idx += 256) {
        int n = idx & 63, k4 = idx >> 6;
        int gn = nb + n;
        float4 v = make_float4(0.f, 0.f, 0.f, 0.f);
        if (gn < N) v = *(const float4*)(pe + (size_t)gn * 64 + 4 * k4);
        sh_inT[(4 * k4 + 0) * 68 + n] = v.x;
        sh_inT[(4 * k4 + 1) * 68 + n] = v.y;
        sh_inT[(4 * k4 + 2) * 68 + n] = v.z;
        sh_inT[(4 * k4 + 3) * 68 + n] = v.w;
    }
    __syncthreads();

    int tr = tid & 7, tc = tid >> 3;
    int r0 = 8 * tr, c0 = 4 * tc;

    ull_t acc[8][2];
    zero_acc(acc);
    gemm_8x4<64, 68, 128>(sh_inT + r0, sh_W + c0, acc);

    float* dst = (c0 < 64) ? g_P : g_Q;
    int lc = c0 & 63;
    float b0 = sh_b[c0], b1 = sh_b[c0 + 1], b2 = sh_b[c0 + 2], b3 = sh_b[c0 + 3];
    #pragma unroll
    for (int i = 0; i < 8; i++) {
        int gn = nb + r0 + i;
        if (gn < N) {
            float o0, o1, o2, o3;
            unpack2(acc[i][0], o0, o1);
            unpack2(acc[i][1], o2, o3);
            *(float4*)(dst + (size_t)gn * 64 + lc) =
                make_float4(o0 + b0, o1 + b1, o2 + b2, o3 + b3);
        }
    }
}

// ============================================================
// Kernel 2: edge kernel — two sequential paths sharing ONE tile
// ============================================================
template <bool IS_TANH>
__device__ __forceinline__ void edge_gemm_path(
    const float* hT, const float* W, const float* bias, const int* recs,
    float* __restrict__ aggr, int r0, int c0, int eb, int E)
{
    ull_t acc[8][2];
    zero_acc(acc);
    gemm_8x4<64, 132, 64>(hT + r0, W + c0, acc);

    float b0 = bias[c0], b1 = bias[c0 + 1], b2 = bias[c0 + 2], b3 = bias[c0 + 3];
    #pragma unroll
    for (int i = 0; i < 8; i++) {
        int el = r0 + i;
        if (eb + el < E) {
            float m0, m1, m2, m3;
            unpack2(acc[i][0], m0, m1);
            unpack2(acc[i][1], m2, m3);
            m0 += b0; m1 += b1; m2 += b2; m3 += b3;
            if (IS_TANH) { m0 = tanh_f(m0); m1 = tanh_f(m1); m2 = tanh_f(m2); m3 = tanh_f(m3); }
            else         { m0 = silu_f(m0); m1 = silu_f(m1); m2 = silu_f(m2); m3 = silu_f(m3); }
            float* dst = aggr + (size_t)recs[el] * 64 + c0;
            asm volatile("red.global.add.v4.f32 [%0], {%1,%2,%3,%4};"
                         :: "l"(dst), "f"(m0), "f"(m1), "f"(m2), "f"(m3) : "memory");
        }
    }
}

__global__ void __launch_bounds__(256, 3) edge_kernel(
    const float* __restrict__ pos,
    const int* __restrict__ ei,          // int32 (JAX demotes int64)
    const float* __restrict__ msg_w1,
    const float* __restrict__ msg_w2, const float* __restrict__ msg_b2,
    const float* __restrict__ mpos_w1,
    const float* __restrict__ mpos_w2, const float* __restrict__ mpos_b2,
    int E)
{
    extern __shared__ float sm[];
    float* sh_t   = sm;                    // [64][132] (reused by both paths)
    float* sh_Wm  = sh_t + 64 * 132;       // [64][64]
    float* sh_Wp  = sh_Wm + 64 * 64;       // [64][64]
    float* sh_we  = sh_Wp + 64 * 64;       // [64]
    float* sh_ve  = sh_we + 64;
    float* sh_bm  = sh_ve + 64;
    float* sh_bp  = sh_bm + 64;
    int*   sh_rec = (int*)(sh_bp + 64);    // [128]

    int tid = threadIdx.x;
    for (int i = tid; i < 64 * 64; i += 256) {
        sh_Wm[i] = msg_w2[i];
        sh_Wp[i] = mpos_w2[i];
    }
    if (tid < 64) {
        sh_we[tid] = msg_w1[256 * 64 + tid];   // dist row of msg_w1
        sh_ve[tid] = mpos_w1[128 * 64 + tid];  // dist row of mpos_w1
        sh_bm[tid] = msg_b2[tid];
        sh_bp[tid] = mpos_b2[tid];
    }

    int eb = blockIdx.x * 128;
    int e  = tid & 127;
    int half = tid >> 7;
    int eg = eb + e;
    bool valid = eg < E;
    int snd = 0, rcv = 0;
    if (valid) { snd = ei[eg]; rcv = ei[E + eg]; }
    if (half == 0) sh_rec[e] = rcv;
    float dist = 0.0f;
    if (valid) {
        float dx = pos[snd * 3 + 0] - pos[rcv * 3 + 0];
        float dy = pos[snd * 3 + 1] - pos[rcv * 3 + 1];
        float dz = pos[snd * 3 + 2] - pos[rcv * 3 + 2];
        dist = sqrtf(dx * dx + dy * dy + dz * dz);
    }
    __syncthreads();   // weights + rec visible to all

    int c0h = half * 32;
    int tr = tid & 15, tc = tid >> 4;      // GEMM map: 8 edges x 4 cols
    int r0 = 8 * tr, c0 = 4 * tc;

    // ---- phase A: silu(A[snd]+B[rcv]+dist*we), msg path ----
    {
        const float4* A4 = (const float4*)(g_A + (size_t)snd * 64 + c0h);
        const float4* B4 = (const float4*)(g_B + (size_t)rcv * 64 + c0h);
        const float4* W4 = (const float4*)(sh_we + c0h);
        #pragma unroll
        for (int j = 0; j < 8; j++) {
            float4 a = A4[j], b = B4[j], w = W4[j];
            float* dst = sh_t + (c0h + 4 * j) * 132 + e;
            dst[0]   = silu_f(a.x + b.x + dist * w.x);
            dst[132] = silu_f(a.y + b.y + dist * w.y);
            dst[264] = silu_f(a.z + b.z + dist * w.z);
            dst[396] = silu_f(a.w + b.w + dist * w.w);
        }
    }
    __syncthreads();
    edge_gemm_path<false>(sh_t, sh_Wm, sh_bm, sh_rec, g_aggr, r0, c0, eb, E);
    __syncthreads();   // all reads of sh_t done before overwrite

    // ---- phase B: tanh(P[snd]+Q[rcv]+dist*ve), pos path ----
    {
        const float4* P4 = (const float4*)(g_P + (size_t)snd * 64 + c0h);
        const float4* Q4 = (const float4*)(g_Q + (size_t)rcv * 64 + c0h);
        const float4* V4 = (const float4*)(sh_ve + c0h);
        #pragma unroll
        for (int j = 0; j < 8; j++) {
            float4 p = P4[j], q = Q4[j], v = V4[j];
            float* dst = sh_t + (c0h + 4 * j) * 132 + e;
            dst[0]   = tanh_f(p.x + q.x + dist * v.x);
            dst[132] = tanh_f(p.y + q.y + dist * v.y);
            dst[264] = tanh_f(p.z + q.z + dist * v.z);
            dst[396] = tanh_f(p.w + q.w + dist * v.w);
        }
    }
    __syncthreads();
    edge_gemm_path<true>(sh_t, sh_Wp, sh_bp, sh_rec, g_aggrp, r0, c0, eb, E);
}

// ============================================================
// Kernel 3a: update = silu([x,pe,aggr]@W1+b1)@W2+b2   (128 nodes/CTA)
// ============================================================
__global__ void __launch_bounds__(256, 3) upd1_kernel(
    const float* __restrict__ x, const float* __restrict__ pe,
    const float* __restrict__ upd_w1, const float* __restrict__ upd_b1,
    const float* __restrict__ upd_w2, const float* __restrict__ upd_b2,
    float* __restrict__ out, int N)
{
    extern __shared__ float sm[];
    float* sh_inT = sm;                    // [64][132] (chunk; later reused as hT)
    float* sh_Wc  = sh_inT + 64 * 132;     // [64][64]
    float* sh_b1  = sh_Wc + 64 * 64;       // [64]
    float* sh_b2  = sh_b1 + 64;            // [64]

    int tid = threadIdx.x;
    int nb = blockIdx.x * 128;
    if (tid < 64) { sh_b1[tid] = upd_b1[tid]; sh_b2[tid] = upd_b2[tid]; }

    int tr = tid & 15, tc = tid >> 4;      // 16 x 16 groups
    int r0 = 8 * tr, c0 = 4 * tc;

    ull_t acc[8][2];
    zero_acc(acc);

    #pragma unroll 1
    for (int ch = 0; ch < 3; ch++) {
        __syncthreads();
        for (int idx = tid; idx < 64 * 64; idx += 256)
            sh_Wc[idx] = upd_w1[ch * 64 * 64 + idx];
        const float* src = (ch == 0) ? x : (ch == 1) ? pe : g_aggr;
        for (int idx = tid; idx < 16 * 128; idx += 256) {
            int n = idx & 127, k4 = idx >> 7;
            int gn = nb + n;
            float4 v = make_float4(0.f, 0.f, 0.f, 0.f);
            if (gn < N) v = *(const float4*)(src + (size_t)gn * 64 + 4 * k4);
            sh_inT[(4 * k4 + 0) * 132 + n] = v.x;
            sh_inT[(4 * k4 + 1) * 132 + n] = v.y;
            sh_inT[(4 * k4 + 2) * 132 + n] = v.z;
            sh_inT[(4 * k4 + 3) * 132 + n] = v.w;
        }
        __syncthreads();
        gemm_8x4<64, 132, 64>(sh_inT + r0, sh_Wc + c0, acc);
    }

    __syncthreads();   // everyone done reading inT before overwrite as hT
    // activation + write hT (over inT buffer); load W2
    #pragma unroll
    for (int j = 0; j < 2; j++) {
        float bj0 = sh_b1[c0 + 2 * j], bj1 = sh_b1[c0 + 2 * j + 1];
        float lo[8], hi[8];
        #pragma unroll
        for (int i = 0; i < 8; i++) { unpack2(acc[i][j], lo[i], hi[i]); }
        float* d0 = sh_inT + (c0 + 2 * j) * 132 + r0;
        float* d1 = d0 + 132;
        *(float4*)(d0)     = make_float4(silu_f(lo[0] + bj0), silu_f(lo[1] + bj0),
                                         silu_f(lo[2] + bj0), silu_f(lo[3] + bj0));
        *(float4*)(d0 + 4) = make_float4(silu_f(lo[4] + bj0), silu_f(lo[5] + bj0),
                                         silu_f(lo[6] + bj0), silu_f(lo[7] + bj0));
        *(float4*)(d1)     = make_float4(silu_f(hi[0] + bj1), silu_f(hi[1] + bj1),
                                         silu_f(hi[2] + bj1), silu_f(hi[3] + bj1));
        *(float4*)(d1 + 4) = make_float4(silu_f(hi[4] + bj1), silu_f(hi[5] + bj1),
                                         silu_f(hi[6] + bj1), silu_f(hi[7] + bj1));
    }
    for (int idx = tid; idx < 64 * 64; idx += 256) sh_Wc[idx] = upd_w2[idx];
    __syncthreads();

    ull_t a2[8][2];
    zero_acc(a2);
    gemm_8x4<64, 132, 64>(sh_inT + r0, sh_Wc + c0, a2);

    float b0 = sh_b2[c0], b1 = sh_b2[c0 + 1], b2 = sh_b2[c0 + 2], b3 = sh_b2[c0 + 3];
    #pragma unroll
    for (int i = 0; i < 8; i++) {
        int g = nb + r0 + i;
        if (g < N) {
            float o0, o1, o2, o3;
            unpack2(a2[i][0], o0, o1);
            unpack2(a2[i][1], o2, o3);
            *(float4*)(out + (size_t)g * 64 + c0) =
                make_float4(o0 + b0, o1 + b1, o2 + b2, o3 + b3);
        }
    }
}

// ============================================================
// Kernel 3b: update_pe = tanh(tanh([pe,aggrp]@W1+b1)@W2+b2)
// ============================================================
__global__ void __launch_bounds__(256, 3) upd2_kernel(
    const float* __restrict__ pe,
    const float* __restrict__ upe_w1, const float* __restrict__ upe_b1,
    const float* __restrict__ upe_w2, const float* __restrict__ upe_b2,
    float* __restrict__ out, int N)
{
    extern __shared__ float sm[];
    float* sh_inT = sm;                    // [64][132]
    float* sh_Wc  = sh_inT + 64 * 132;     // [64][64]
    float* sh_b1  = sh_Wc + 64 * 64;
    float* sh_b2  = sh_b1 + 64;

    int tid = threadIdx.x;
    int nb = blockIdx.x * 128;
    if (tid < 64) { sh_b1[tid] = upe_b1[tid]; sh_b2[tid] = upe_b2[tid]; }

    int tr = tid & 15, tc = tid >> 4;
    int r0 = 8 * tr, c0 = 4 * tc;

    ull_t acc[8][2];
    zero_acc(acc);

    #pragma unroll 1
    for (int ch = 0; ch < 2; ch++) {
        __syncthreads();
        for (int idx = tid; idx < 64 * 64; idx += 256)
            sh_Wc[idx] = upe_w1[ch * 64 * 64 + idx];
        const float* src = (ch == 0) ? pe : g_aggrp;
        for (int idx = tid; idx < 16 * 128; idx += 256) {
            int n = idx & 127, k4 = idx >> 7;
            int gn = nb + n;
            float4 v = make_float4(0.f, 0.f, 0.f, 0.f);
            if (gn < N) v = *(const float4*)(src + (size_t)gn * 64 + 4 * k4);
            sh_inT[(4 * k4 + 0) * 132 + n] = v.x;
            sh_inT[(4 * k4 + 1) * 132 + n] = v.y;
            sh_inT[(4 * k4 + 2) * 132 + n] = v.z;
            sh_inT[(4 * k4 + 3) * 132 + n] = v.w;
        }
        __syncthreads();
        gemm_8x4<64, 132, 64>(sh_inT + r0, sh_Wc + c0, acc);
    }

    __syncthreads();
    #pragma unroll
    for (int j = 0; j < 2; j++) {
        float bj0 = sh_b1[c0 + 2 * j], bj1 = sh_b1[c0 + 2 * j + 1];
        float lo[8], hi[8];
        #pragma unroll
        for (int i = 0; i < 8; i++) { unpack2(acc[i][j], lo[i], hi[i]); }
        float* d0 = sh_inT + (c0 + 2 * j) * 132 + r0;
        float* d1 = d0 + 132;
        *(float4*)(d0)     = make_float4(tanh_f(lo[0] + bj0), tanh_f(lo[1] + bj0),
                                         tanh_f(lo[2] + bj0), tanh_f(lo[3] + bj0));
        *(float4*)(d0 + 4) = make_float4(tanh_f(lo[4] + bj0), tanh_f(lo[5] + bj0),
                                         tanh_f(lo[6] + bj0), tanh_f(lo[7] + bj0));
        *(float4*)(d1)     = make_float4(tanh_f(hi[0] + bj1), tanh_f(hi[1] + bj1),
                                         tanh_f(hi[2] + bj1), tanh_f(hi[3] + bj1));
        *(float4*)(d1 + 4) = make_float4(tanh_f(hi[4] + bj1), tanh_f(hi[5] + bj1),
                                         tanh_f(hi[6] + bj1), tanh_f(hi[7] + bj1));
    }
    for (int idx = tid; idx < 64 * 64; idx += 256) sh_Wc[idx] = upe_w2[idx];
    __syncthreads();

    ull_t a2[8][2];
    zero_acc(a2);
    gemm_8x4<64, 132, 64>(sh_inT + r0, sh_Wc + c0, a2);

    float b0 = sh_b2[c0], b1 = sh_b2[c0 + 1], b2 = sh_b2[c0 + 2], b3 = sh_b2[c0 + 3];
    float* out2 = out + (size_t)N * 64;
    #pragma unroll
    for (int i = 0; i < 8; i++) {
        int g = nb + r0 + i;
        if (g < N) {
            float o0, o1, o2, o3;
            unpack2(a2[i][0], o0, o1);
            unpack2(a2[i][1], o2, o3);
            *(float4*)(out2 + (size_t)g * 64 + c0) =
                make_float4(tanh_f(o0 + b0), tanh_f(o1 + b1),
                            tanh_f(o2 + b2), tanh_f(o3 + b3));
        }
    }
}

// ============================================================
// Host launch
// ============================================================
extern "C" void kernel_launch(void* const* d_in, const int* in_sizes, int n_in,
                              void* d_out, int out_size)
{
    const float* x       = (const float*)d_in[0];
    const float* pos     = (const float*)d_in[1];
    const float* pe      = (const float*)d_in[2];
    const int*   ei      = (const int*)d_in[3];
    const float* msg_w1  = (const float*)d_in[4];
    const float* msg_b1  = (const float*)d_in[5];
    const float* msg_w2  = (const float*)d_in[6];
    const float* msg_b2  = (const float*)d_in[7];
    const float* mpos_w1 = (const float*)d_in[8];
    const float* mpos_b1 = (const float*)d_in[9];
    const float* mpos_w2 = (const float*)d_in[10];
    const float* mpos_b2 = (const float*)d_in[11];
    const float* upd_w1  = (const float*)d_in[12];
    const float* upd_b1  = (const float*)d_in[13];
    const float* upd_w2  = (const float*)d_in[14];
    const float* upd_b2  = (const float*)d_in[15];
    const float* upe_w1  = (const float*)d_in[16];
    const float* upe_b1  = (const float*)d_in[17];
    const float* upe_w2  = (const float*)d_in[18];
    const float* upe_b2  = (const float*)d_in[19];

    int N = in_sizes[0] / 64;
    int E = in_sizes[3] / 2;

    const int SMEM_AB   = (64 * 68 + 64 * 128 + 128) * 4;              // 50,688 B
    const int SMEM_PQ   = SMEM_AB;                                     // 50,688 B
    const int SMEM_EDGE = (64 * 132 + 64 * 64 * 2 + 256) * 4 + 512;    // 68,096 B
    const int SMEM_UPD  = (64 * 132 + 64 * 64 + 128) * 4;              // 50,688 B

    cudaFuncSetAttribute(pre_AB_kernel, cudaFuncAttributeMaxDynamicSharedMemorySize, SMEM_AB);
    cudaFuncSetAttribute(pre_PQ_kernel, cudaFuncAttributeMaxDynamicSharedMemorySize, SMEM_PQ);
    cudaFuncSetAttribute(edge_kernel,   cudaFuncAttributeMaxDynamicSharedMemorySize, SMEM_EDGE);
    cudaFuncSetAttribute(upd1_kernel,   cudaFuncAttributeMaxDynamicSharedMemorySize, SMEM_UPD);
    cudaFuncSetAttribute(upd2_kernel,   cudaFuncAttributeMaxDynamicSharedMemorySize, SMEM_UPD);

    int gn64  = (N + 63) / 64;
    int gn128 = (N + 127) / 128;
    pre_AB_kernel<<<gn64, 256, SMEM_AB>>>(x, pe, msg_w1, msg_b1, N);
    pre_PQ_kernel<<<gn64, 256, SMEM_PQ>>>(pe, mpos_w1, mpos_b1, N);
    edge_kernel<<<(E + 127) / 128, 256, SMEM_EDGE>>>(pos, ei, msg_w1, msg_w2, msg_b2,
                                                     mpos_w1, mpos_w2, mpos_b2, E);
    upd1_kernel<<<gn128, 256, SMEM_UPD>>>(x, pe, upd_w1, upd_b1, upd_w2, upd_b2,
                                          (float*)d_out, N);
    upd2_kernel<<<gn128, 256, SMEM_UPD>>>(pe, upe_w1, upe_b1, upe_w2, upe_b2,
                                          (float*)d_out, N);
}

// round 8
// speedup vs baseline: 1.2687x; 1.2687x over previous
#include <cuda_runtime.h>

#define NV_MAX 50000
#define HDIM 64

// -------- scratch (no allocs allowed) --------
__device__ float g_A[NV_MAX * HDIM];      // x@W0 + pe@W1   (msg, send side)
__device__ float g_B[NV_MAX * HDIM];      // x@W2 + pe@W3   (msg, recv side)
__device__ float g_P[NV_MAX * HDIM];      // pe@V0          (pos, send side)
__device__ float g_Q[NV_MAX * HDIM];      // pe@V1          (pos, recv side)
__device__ float g_aggr[NV_MAX * HDIM];
__device__ float g_aggrp[NV_MAX * HDIM];

typedef unsigned long long ull_t;

__device__ __forceinline__ ull_t pack2(float lo, float hi) {
    ull_t r; asm("mov.b64 %0, {%1, %2};" : "=l"(r) : "f"(lo), "f"(hi)); return r;
}
__device__ __forceinline__ void unpack2(ull_t v, float& lo, float& hi) {
    asm("mov.b64 {%0, %1}, %2;" : "=f"(lo), "=f"(hi) : "l"(v));
}
__device__ __forceinline__ ull_t ffma2(ull_t a, ull_t b, ull_t c) {
    ull_t d; asm("fma.rn.f32x2 %0, %1, %2, %3;" : "=l"(d) : "l"(a), "l"(b), "l"(c)); return d;
}
__device__ __forceinline__ float tanh_f(float x) {
    float y; asm("tanh.approx.f32 %0, %1;" : "=f"(y) : "f"(x)); return y;
}
__device__ __forceinline__ float silu_f(float x) {
    return 0.5f * x * (1.0f + tanh_f(0.5f * x));   // single MUFU
}

// ------------------------------------------------------------
// Core microkernel: 8 rows x 4 cols per thread, software-pipelined.
// Rows split as two warp-contiguous groups: [r0..r0+3] and [HALF+r0..HALF+r0+3]
// with r0 = 4*tr  ->  conflict-free LDS.128 across the warp.
//   inT: [K][ISTRIDE], pre-offset by r0;  W: [K][WSTRIDE], pre-offset by c0.
// ------------------------------------------------------------
template <int K, int ISTRIDE, int WSTRIDE, int HALF>
__device__ __forceinline__ void gemm_8x4(
    const float* __restrict__ inT, const float* __restrict__ W, ull_t acc[8][2])
{
    float4 ha = *(const float4*)(inT);
    float4 hb = *(const float4*)(inT + HALF);
    ulonglong2 w = *(const ulonglong2*)(W);
    #pragma unroll 8
    for (int k = 0; k < K; k++) {
        float4 nha, nhb; ulonglong2 nw;
        if (k + 1 < K) {
            nha = *(const float4*)(inT + (k + 1) * ISTRIDE);
            nhb = *(const float4*)(inT + (k + 1) * ISTRIDE + HALF);
            nw  = *(const ulonglong2*)(W + (k + 1) * WSTRIDE);
        }
        ull_t p0 = pack2(ha.x, ha.x), p1 = pack2(ha.y, ha.y);
        ull_t p2 = pack2(ha.z, ha.z), p3 = pack2(ha.w, ha.w);
        ull_t p4 = pack2(hb.x, hb.x), p5 = pack2(hb.y, hb.y);
        ull_t p6 = pack2(hb.z, hb.z), p7 = pack2(hb.w, hb.w);
        acc[0][0] = ffma2(p0, w.x, acc[0][0]); acc[0][1] = ffma2(p0, w.y, acc[0][1]);
        acc[1][0] = ffma2(p1, w.x, acc[1][0]); acc[1][1] = ffma2(p1, w.y, acc[1][1]);
        acc[2][0] = ffma2(p2, w.x, acc[2][0]); acc[2][1] = ffma2(p2, w.y, acc[2][1]);
        acc[3][0] = ffma2(p3, w.x, acc[3][0]); acc[3][1] = ffma2(p3, w.y, acc[3][1]);
        acc[4][0] = ffma2(p4, w.x, acc[4][0]); acc[4][1] = ffma2(p4, w.y, acc[4][1]);
        acc[5][0] = ffma2(p5, w.x, acc[5][0]); acc[5][1] = ffma2(p5, w.y, acc[5][1]);
        acc[6][0] = ffma2(p6, w.x, acc[6][0]); acc[6][1] = ffma2(p6, w.y, acc[6][1]);
        acc[7][0] = ffma2(p7, w.x, acc[7][0]); acc[7][1] = ffma2(p7, w.y, acc[7][1]);
        ha = nha; hb = nhb; w = nw;
    }
}

__device__ __forceinline__ void zero_acc(ull_t acc[8][2]) {
    #pragma unroll
    for (int i = 0; i < 8; i++) { acc[i][0] = 0ULL; acc[i][1] = 0ULL; }
}

// ============================================================
// Kernel 1a: pre_AB — A,B projections (+ zero aggr buffers)
//   64 nodes/CTA; K=128 ([x;pe]) in 2 chunks; 128 out cols (A|B).
//   tr = tid&7 (rows: 4*tr and 32+4*tr), tc = tid>>3 (c0 = 4*tc).
// ============================================================
__global__ void __launch_bounds__(256, 3) pre_AB_kernel(
    const float* __restrict__ x, const float* __restrict__ pe,
    const float* __restrict__ msg_w1, const float* __restrict__ msg_b1,
    int N)
{
    extern __shared__ float sm[];
    float* sh_inT = sm;                   // [64][68]
    float* sh_Wc  = sh_inT + 64 * 68;     // [64][128]
    float* sh_b   = sh_Wc + 64 * 128;     // [128]

    int tid = threadIdx.x;
    int nb = blockIdx.x * 64;
    if (tid < 128) sh_b[tid] = (tid < 64) ? msg_b1[tid] : 0.0f;

    // zero aggregation buffers for this CTA's nodes (before edge kernel)
    for (int idx = tid; idx < 2048; idx += 256) {
        int n = idx & 63, s = (idx >> 6) & 15, which = idx >> 10;
        int gn = nb + n;
        if (gn < N) {
            float4* dst = (float4*)((which ? g_aggrp : g_aggr) + (size_t)gn * 64) + s;
            *dst = make_float4(0.f, 0.f, 0.f, 0.f);
        }
    }

    int tr = tid & 7, tc = tid >> 3;
    int r0 = 4 * tr, c0 = 4 * tc;

    ull_t acc[8][2];
    zero_acc(acc);

    #pragma unroll 1
    for (int ch = 0; ch < 2; ch++) {
        __syncthreads();
        for (int idx = tid; idx < 64 * 128; idx += 256) {
            int k = idx >> 7, c = idx & 127;
            sh_Wc[idx] = (c < 64) ? msg_w1[(ch * 64 + k) * 64 + c]
                                  : msg_w1[(128 + ch * 64 + k) * 64 + (c - 64)];
        }
        const float* src = (ch == 0) ? x : pe;
        for (int idx = tid; idx < 16 * 64; idx += 256) {
            int n = idx & 63, k4 = idx >> 6;
            int gn = nb + n;
            float4 v = make_float4(0.f, 0.f, 0.f, 0.f);
            if (gn < N) v = *(const float4*)(src + (size_t)gn * 64 + 4 * k4);
            sh_inT[(4 * k4 + 0) * 68 + n] = v.x;
            sh_inT[(4 * k4 + 1) * 68 + n] = v.y;
            sh_inT[(4 * k4 + 2) * 68 + n] = v.z;
            sh_inT[(4 * k4 + 3) * 68 + n] = v.w;
        }
        __syncthreads();
        gemm_8x4<64, 68, 128, 32>(sh_inT + r0, sh_Wc + c0, acc);
    }

    float* dst = (c0 < 64) ? g_A : g_B;
    int lc = c0 & 63;
    float b0 = sh_b[c0], b1 = sh_b[c0 + 1], b2 = sh_b[c0 + 2], b3 = sh_b[c0 + 3];
    #pragma unroll
    for (int i = 0; i < 8; i++) {
        int rr = (i < 4) ? (r0 + i) : (32 + r0 + i - 4);
        int gn = nb + rr;
        if (gn < N) {
            float o0, o1, o2, o3;
            unpack2(acc[i][0], o0, o1);
            unpack2(acc[i][1], o2, o3);
            *(float4*)(dst + (size_t)gn * 64 + lc) =
                make_float4(o0 + b0, o1 + b1, o2 + b2, o3 + b3);
        }
    }
}

// ============================================================
// Kernel 1b: pre_PQ — P,Q projections; 64 nodes/CTA, K=64 (pe)
// ============================================================
__global__ void __launch_bounds__(256, 3) pre_PQ_kernel(
    const float* __restrict__ pe,
    const float* __restrict__ mpos_w1, const float* __restrict__ mpos_b1,
    int N)
{
    extern __shared__ float sm[];
    float* sh_inT = sm;                   // [64][68]
    float* sh_W   = sh_inT + 64 * 68;     // [64][128]
    float* sh_b   = sh_W + 64 * 128;      // [128]

    int tid = threadIdx.x;
    int nb = blockIdx.x * 64;
    if (tid < 128) sh_b[tid] = (tid < 64) ? mpos_b1[tid] : 0.0f;

    for (int idx = tid; idx < 64 * 128; idx += 256) {
        int k = idx >> 7, c = idx & 127;
        sh_W[idx] = (c < 64) ? mpos_w1[k * 64 + c]
                             : mpos_w1[(64 + k) * 64 + (c - 64)];
    }
    for (int idx = tid; idx < 16 * 64; idx += 256) {
        int n = idx & 63, k4 = idx >> 6;
        int gn = nb + n;
        float4 v = make_float4(0.f, 0.f, 0.f, 0.f);
        if (gn < N) v = *(const float4*)(pe + (size_t)gn * 64 + 4 * k4);
        sh_inT[(4 * k4 + 0) * 68 + n] = v.x;
        sh_inT[(4 * k4 + 1) * 68 + n] = v.y;
        sh_inT[(4 * k4 + 2) * 68 + n] = v.z;
        sh_inT[(4 * k4 + 3) * 68 + n] = v.w;
    }
    __syncthreads();

    int tr = tid & 7, tc = tid >> 3;
    int r0 = 4 * tr, c0 = 4 * tc;

    ull_t acc[8][2];
    zero_acc(acc);
    gemm_8x4<64, 68, 128, 32>(sh_inT + r0, sh_W + c0, acc);

    float* dst = (c0 < 64) ? g_P : g_Q;
    int lc = c0 & 63;
    float b0 = sh_b[c0], b1 = sh_b[c0 + 1], b2 = sh_b[c0 + 2], b3 = sh_b[c0 + 3];
    #pragma unroll
    for (int i = 0; i < 8; i++) {
        int rr = (i < 4) ? (r0 + i) : (32 + r0 + i - 4);
        int gn = nb + rr;
        if (gn < N) {
            float o0, o1, o2, o3;
            unpack2(acc[i][0], o0, o1);
            unpack2(acc[i][1], o2, o3);
            *(float4*)(dst + (size_t)gn * 64 + lc) =
                make_float4(o0 + b0, o1 + b1, o2 + b2, o3 + b3);
        }
    }
}

// ============================================================
// Kernel 2: edge kernel — two sequential paths sharing ONE tile
//   128 edges/CTA; GEMM rows split [4*tr..] and [64+4*tr..].
// ============================================================
template <bool IS_TANH>
__device__ __forceinline__ void edge_gemm_path(
    const float* hT, const float* W, const float* bias, const int* recs,
    float* __restrict__ aggr, int r0, int c0, int eb, int E)
{
    ull_t acc[8][2];
    zero_acc(acc);
    gemm_8x4<64, 132, 64, 64>(hT + r0, W + c0, acc);

    float b0 = bias[c0], b1 = bias[c0 + 1], b2 = bias[c0 + 2], b3 = bias[c0 + 3];
    #pragma unroll
    for (int i = 0; i < 8; i++) {
        int el = (i < 4) ? (r0 + i) : (64 + r0 + i - 4);
        if (eb + el < E) {
            float m0, m1, m2, m3;
            unpack2(acc[i][0], m0, m1);
            unpack2(acc[i][1], m2, m3);
            m0 += b0; m1 += b1; m2 += b2; m3 += b3;
            if (IS_TANH) { m0 = tanh_f(m0); m1 = tanh_f(m1); m2 = tanh_f(m2); m3 = tanh_f(m3); }
            else         { m0 = silu_f(m0); m1 = silu_f(m1); m2 = silu_f(m2); m3 = silu_f(m3); }
            float* dst = aggr + (size_t)recs[el] * 64 + c0;
            asm volatile("red.global.add.v4.f32 [%0], {%1,%2,%3,%4};"
                         :: "l"(dst), "f"(m0), "f"(m1), "f"(m2), "f"(m3) : "memory");
        }
    }
}

__global__ void __launch_bounds__(256, 3) edge_kernel(
    const float* __restrict__ pos,
    const int* __restrict__ ei,          // int32 (JAX demotes int64)
    const float* __restrict__ msg_w1,
    const float* __restrict__ msg_w2, const float* __restrict__ msg_b2,
    const float* __restrict__ mpos_w1,
    const float* __restrict__ mpos_w2, const float* __restrict__ mpos_b2,
    int E)
{
    extern __shared__ float sm[];
    float* sh_t   = sm;                    // [64][132] (reused by both paths)
    float* sh_Wm  = sh_t + 64 * 132;       // [64][64]
    float* sh_Wp  = sh_Wm + 64 * 64;       // [64][64]
    float* sh_we  = sh_Wp + 64 * 64;       // [64]
    float* sh_ve  = sh_we + 64;
    float* sh_bm  = sh_ve + 64;
    float* sh_bp  = sh_bm + 64;
    int*   sh_rec = (int*)(sh_bp + 64);    // [128]

    int tid = threadIdx.x;
    for (int i = tid; i < 64 * 64; i += 256) {
        sh_Wm[i] = msg_w2[i];
        sh_Wp[i] = mpos_w2[i];
    }
    if (tid < 64) {
        sh_we[tid] = msg_w1[256 * 64 + tid];   // dist row of msg_w1
        sh_ve[tid] = mpos_w1[128 * 64 + tid];  // dist row of mpos_w1
        sh_bm[tid] = msg_b2[tid];
        sh_bp[tid] = mpos_b2[tid];
    }

    int eb = blockIdx.x * 128;
    int e  = tid & 127;
    int half = tid >> 7;
    int eg = eb + e;
    bool valid = eg < E;
    int snd = 0, rcv = 0;
    if (valid) { snd = ei[eg]; rcv = ei[E + eg]; }
    if (half == 0) sh_rec[e] = rcv;
    float dist = 0.0f;
    if (valid) {
        float dx = pos[snd * 3 + 0] - pos[rcv * 3 + 0];
        float dy = pos[snd * 3 + 1] - pos[rcv * 3 + 1];
        float dz = pos[snd * 3 + 2] - pos[rcv * 3 + 2];
        dist = sqrtf(dx * dx + dy * dy + dz * dz);
    }
    __syncthreads();   // weights + rec visible to all

    int c0h = half * 32;
    int tr = tid & 15, tc = tid >> 4;      // GEMM map: rows 4*tr / 64+4*tr, c0=4*tc
    int r0 = 4 * tr, c0 = 4 * tc;

    // ---- phase A: silu(A[snd]+B[rcv]+dist*we), msg path ----
    {
        const float4* A4 = (const float4*)(g_A + (size_t)snd * 64 + c0h);
        const float4* B4 = (const float4*)(g_B + (size_t)rcv * 64 + c0h);
        const float4* W4 = (const float4*)(sh_we + c0h);
        #pragma unroll
        for (int j = 0; j < 8; j++) {
            float4 a = A4[j], b = B4[j], w = W4[j];
            float* dst = sh_t + (c0h + 4 * j) * 132 + e;
            dst[0]   = silu_f(a.x + b.x + dist * w.x);
            dst[132] = silu_f(a.y + b.y + dist * w.y);
            dst[264] = silu_f(a.z + b.z + dist * w.z);
            dst[396] = silu_f(a.w + b.w + dist * w.w);
        }
    }
    __syncthreads();
    edge_gemm_path<false>(sh_t, sh_Wm, sh_bm, sh_rec, g_aggr, r0, c0, eb, E);
    __syncthreads();   // all reads of sh_t done before overwrite

    // ---- phase B: tanh(P[snd]+Q[rcv]+dist*ve), pos path ----
    {
        const float4* P4 = (const float4*)(g_P + (size_t)snd * 64 + c0h);
        const float4* Q4 = (const float4*)(g_Q + (size_t)rcv * 64 + c0h);
        const float4* V4 = (const float4*)(sh_ve + c0h);
        #pragma unroll
        for (int j = 0; j < 8; j++) {
            float4 p = P4[j], q = Q4[j], v = V4[j];
            float* dst = sh_t + (c0h + 4 * j) * 132 + e;
            dst[0]   = tanh_f(p.x + q.x + dist * v.x);
            dst[132] = tanh_f(p.y + q.y + dist * v.y);
            dst[264] = tanh_f(p.z + q.z + dist * v.z);
            dst[396] = tanh_f(p.w + q.w + dist * v.w);
        }
    }
    __syncthreads();
    edge_gemm_path<true>(sh_t, sh_Wp, sh_bp, sh_rec, g_aggrp, r0, c0, eb, E);
}

// ============================================================
// Kernel 3a: update = silu([x,pe,aggr]@W1+b1)@W2+b2   (128 nodes/CTA)
// ============================================================
__global__ void __launch_bounds__(256, 3) upd1_kernel(
    const float* __restrict__ x, const float* __restrict__ pe,
    const float* __restrict__ upd_w1, const float* __restrict__ upd_b1,
    const float* __restrict__ upd_w2, const float* __restrict__ upd_b2,
    float* __restrict__ out, int N)
{
    extern __shared__ float sm[];
    float* sh_inT = sm;                    // [64][132] (chunk; later reused as hT)
    float* sh_Wc  = sh_inT + 64 * 132;     // [64][64]
    float* sh_b1  = sh_Wc + 64 * 64;       // [64]
    float* sh_b2  = sh_b1 + 64;            // [64]

    int tid = threadIdx.x;
    int nb = blockIdx.x * 128;
    if (tid < 64) { sh_b1[tid] = upd_b1[tid]; sh_b2[tid] = upd_b2[tid]; }

    int tr = tid & 15, tc = tid >> 4;
    int r0 = 4 * tr, c0 = 4 * tc;

    ull_t acc[8][2];
    zero_acc(acc);

    #pragma unroll 1
    for (int ch = 0; ch < 3; ch++) {
        __syncthreads();
        for (int idx = tid; idx < 64 * 64; idx += 256)
            sh_Wc[idx] = upd_w1[ch * 64 * 64 + idx];
        const float* src = (ch == 0) ? x : (ch == 1) ? pe : g_aggr;
        for (int idx = tid; idx < 16 * 128; idx += 256) {
            int n = idx & 127, k4 = idx >> 7;
            int gn = nb + n;
            float4 v = make_float4(0.f, 0.f, 0.f, 0.f);
            if (gn < N) v = *(const float4*)(src + (size_t)gn * 64 + 4 * k4);
            sh_inT[(4 * k4 + 0) * 132 + n] = v.x;
            sh_inT[(4 * k4 + 1) * 132 + n] = v.y;
            sh_inT[(4 * k4 + 2) * 132 + n] = v.z;
            sh_inT[(4 * k4 + 3) * 132 + n] = v.w;
        }
        __syncthreads();
        gemm_8x4<64, 132, 64, 64>(sh_inT + r0, sh_Wc + c0, acc);
    }

    __syncthreads();   // everyone done reading inT before overwrite as hT
    // activation + write hT (over inT buffer): row i -> node row rr
    #pragma unroll
    for (int j = 0; j < 2; j++) {
        float bj0 = sh_b1[c0 + 2 * j], bj1 = sh_b1[c0 + 2 * j + 1];
        float lo[8], hi[8];
        #pragma unroll
        for (int i = 0; i < 8; i++) { unpack2(acc[i][j], lo[i], hi[i]); }
        float* d0 = sh_inT + (c0 + 2 * j) * 132;
        float* d1 = d0 + 132;
        *(float4*)(d0 + r0)      = make_float4(silu_f(lo[0] + bj0), silu_f(lo[1] + bj0),
                                               silu_f(lo[2] + bj0), silu_f(lo[3] + bj0));
        *(float4*)(d0 + 64 + r0) = make_float4(silu_f(lo[4] + bj0), silu_f(lo[5] + bj0),
                                               silu_f(lo[6] + bj0), silu_f(lo[7] + bj0));
        *(float4*)(d1 + r0)      = make_float4(silu_f(hi[0] + bj1), silu_f(hi[1] + bj1),
                                               silu_f(hi[2] + bj1), silu_f(hi[3] + bj1));
        *(float4*)(d1 + 64 + r0) = make_float4(silu_f(hi[4] + bj1), silu_f(hi[5] + bj1),
                                               silu_f(hi[6] + bj1), silu_f(hi[7] + bj1));
    }
    for (int idx = tid; idx < 64 * 64; idx += 256) sh_Wc[idx] = upd_w2[idx];
    __syncthreads();

    ull_t a2[8][2];
    zero_acc(a2);
    gemm_8x4<64, 132, 64, 64>(sh_inT + r0, sh_Wc + c0, a2);

    float b0 = sh_b2[c0], b1 = sh_b2[c0 + 1], b2 = sh_b2[c0 + 2], b3 = sh_b2[c0 + 3];
    #pragma unroll
    for (int i = 0; i < 8; i++) {
        int rr = (i < 4) ? (r0 + i) : (64 + r0 + i - 4);
        int g = nb + rr;
        if (g < N) {
            float o0, o1, o2, o3;
            unpack2(a2[i][0], o0, o1);
            unpack2(a2[i][1], o2, o3);
            *(float4*)(out + (size_t)g * 64 + c0) =
                make_float4(o0 + b0, o1 + b1, o2 + b2, o3 + b3);
        }
    }
}

// ============================================================
// Kernel 3b: update_pe = tanh(tanh([pe,aggrp]@W1+b1)@W2+b2)
// ============================================================
__global__ void __launch_bounds__(256, 3) upd2_kernel(
    const float* __restrict__ pe,
    const float* __restrict__ upe_w1, const float* __restrict__ upe_b1,
    const float* __restrict__ upe_w2, const float* __restrict__ upe_b2,
    float* __restrict__ out, int N)
{
    extern __shared__ float sm[];
    float* sh_inT = sm;                    // [64][132]
    float* sh_Wc  = sh_inT + 64 * 132;     // [64][64]
    float* sh_b1  = sh_Wc + 64 * 64;
    float* sh_b2  = sh_b1 + 64;

    int tid = threadIdx.x;
    int nb = blockIdx.x * 128;
    if (tid < 64) { sh_b1[tid] = upe_b1[tid]; sh_b2[tid] = upe_b2[tid]; }

    int tr = tid & 15, tc = tid >> 4;
    int r0 = 4 * tr, c0 = 4 * tc;

    ull_t acc[8][2];
    zero_acc(acc);

    #pragma unroll 1
    for (int ch = 0; ch < 2; ch++) {
        __syncthreads();
        for (int idx = tid; idx < 64 * 64; idx += 256)
            sh_Wc[idx] = upe_w1[ch * 64 * 64 + idx];
        const float* src = (ch == 0) ? pe : g_aggrp;
        for (int idx = tid; idx < 16 * 128; idx += 256) {
            int n = idx & 127, k4 = idx >> 7;
            int gn = nb + n;
            float4 v = make_float4(0.f, 0.f, 0.f, 0.f);
            if (gn < N) v = *(const float4*)(src + (size_t)gn * 64 + 4 * k4);
            sh_inT[(4 * k4 + 0) * 132 + n] = v.x;
            sh_inT[(4 * k4 + 1) * 132 + n] = v.y;
            sh_inT[(4 * k4 + 2) * 132 + n] = v.z;
            sh_inT[(4 * k4 + 3) * 132 + n] = v.w;
        }
        __syncthreads();
        gemm_8x4<64, 132, 64, 64>(sh_inT + r0, sh_Wc + c0, acc);
    }

    __syncthreads();
    #pragma unroll
    for (int j = 0; j < 2; j++) {
        float bj0 = sh_b1[c0 + 2 * j], bj1 = sh_b1[c0 + 2 * j + 1];
        float lo[8], hi[8];
        #pragma unroll
        for (int i = 0; i < 8; i++) { unpack2(acc[i][j], lo[i], hi[i]); }
        float* d0 = sh_inT + (c0 + 2 * j) * 132;
        float* d1 = d0 + 132;
        *(float4*)(d0 + r0)      = make_float4(tanh_f(lo[0] + bj0), tanh_f(lo[1] + bj0),
                                               tanh_f(lo[2] + bj0), tanh_f(lo[3] + bj0));
        *(float4*)(d0 + 64 + r0) = make_float4(tanh_f(lo[4] + bj0), tanh_f(lo[5] + bj0),
                                               tanh_f(lo[6] + bj0), tanh_f(lo[7] + bj0));
        *(float4*)(d1 + r0)      = make_float4(tanh_f(hi[0] + bj1), tanh_f(hi[1] + bj1),
                                               tanh_f(hi[2] + bj1), tanh_f(hi[3] + bj1));
        *(float4*)(d1 + 64 + r0) = make_float4(tanh_f(hi[4] + bj1), tanh_f(hi[5] + bj1),
                                               tanh_f(hi[6] + bj1), tanh_f(hi[7] + bj1));
    }
    for (int idx = tid; idx < 64 * 64; idx += 256) sh_Wc[idx] = upe_w2[idx];
    __syncthreads();

    ull_t a2[8][2];
    zero_acc(a2);
    gemm_8x4<64, 132, 64, 64>(sh_inT + r0, sh_Wc + c0, a2);

    float b0 = sh_b2[c0], b1 = sh_b2[c0 + 1], b2 = sh_b2[c0 + 2], b3 = sh_b2[c0 + 3];
    float* out2 = out + (size_t)N * 64;
    #pragma unroll
    for (int i = 0; i < 8; i++) {
        int rr = (i < 4) ? (r0 + i) : (64 + r0 + i - 4);
        int g = nb + rr;
        if (g < N) {
            float o0, o1, o2, o3;
            unpack2(a2[i][0], o0, o1);
            unpack2(a2[i][1], o2, o3);
            *(float4*)(out2 + (size_t)g * 64 + c0) =
                make_float4(tanh_f(o0 + b0), tanh_f(o1 + b1),
                            tanh_f(o2 + b2), tanh_f(o3 + b3));
        }
    }
}

// ============================================================
// Host launch
// ============================================================
extern "C" void kernel_launch(void* const* d_in, const int* in_sizes, int n_in,
                              void* d_out, int out_size)
{
    const float* x       = (const float*)d_in[0];
    const float* pos     = (const float*)d_in[1];
    const float* pe      = (const float*)d_in[2];
    const int*   ei      = (const int*)d_in[3];
    const float* msg_w1  = (const float*)d_in[4];
    const float* msg_b1  = (const float*)d_in[5];
    const float* msg_w2  = (const float*)d_in[6];
    const float* msg_b2  = (const float*)d_in[7];
    const float* mpos_w1 = (const float*)d_in[8];
    const float* mpos_b1 = (const float*)d_in[9];
    const float* mpos_w2 = (const float*)d_in[10];
    const float* mpos_b2 = (const float*)d_in[11];
    const float* upd_w1  = (const float*)d_in[12];
    const float* upd_b1  = (const float*)d_in[13];
    const float* upd_w2  = (const float*)d_in[14];
    const float* upd_b2  = (const float*)d_in[15];
    const float* upe_w1  = (const float*)d_in[16];
    const float* upe_b1  = (const float*)d_in[17];
    const float* upe_w2  = (const float*)d_in[18];
    const float* upe_b2  = (const float*)d_in[19];

    int N = in_sizes[0] / 64;
    int E = in_sizes[3] / 2;

    const int SMEM_AB   = (64 * 68 + 64 * 128 + 128) * 4;              // 50,688 B
    const int SMEM_PQ   = SMEM_AB;
    const int SMEM_EDGE = (64 * 132 + 64 * 64 * 2 + 256) * 4 + 512;    // 68,096 B
    const int SMEM_UPD  = (64 * 132 + 64 * 64 + 128) * 4;              // 50,688 B

    cudaFuncSetAttribute(pre_AB_kernel, cudaFuncAttributeMaxDynamicSharedMemorySize, SMEM_AB);
    cudaFuncSetAttribute(pre_PQ_kernel, cudaFuncAttributeMaxDynamicSharedMemorySize, SMEM_PQ);
    cudaFuncSetAttribute(edge_kernel,   cudaFuncAttributeMaxDynamicSharedMemorySize, SMEM_EDGE);
    cudaFuncSetAttribute(upd1_kernel,   cudaFuncAttributeMaxDynamicSharedMemorySize, SMEM_UPD);
    cudaFuncSetAttribute(upd2_kernel,   cudaFuncAttributeMaxDynamicSharedMemorySize, SMEM_UPD);

    int gn64  = (N + 63) / 64;
    int gn128 = (N + 127) / 128;
    pre_AB_kernel<<<gn64, 256, SMEM_AB>>>(x, pe, msg_w1, msg_b1, N);
    pre_PQ_kernel<<<gn64, 256, SMEM_PQ>>>(pe, mpos_w1, mpos_b1, N);
    edge_kernel<<<(E + 127) / 128, 256, SMEM_EDGE>>>(pos, ei, msg_w1, msg_w2, msg_b2,
                                                     mpos_w1, mpos_w2, mpos_b2, E);
    upd1_kernel<<<gn128, 256, SMEM_UPD>>>(x, pe, upd_w1, upd_b1, upd_w2, upd_b2,
                                          (float*)d_out, N);
    upd2_kernel<<<gn128, 256, SMEM_UPD>>>(pe, upe_w1, upe_b1, upe_w2, upe_b2,
                                          (float*)d_out, N);
}

// round 9
// speedup vs baseline: 1.3733x; 1.0824x over previous
#include <cuda_runtime.h>

#define NV_MAX 50000
#define HDIM 64

// -------- scratch (no allocs allowed) --------
__device__ float g_A[NV_MAX * HDIM];
__device__ float g_B[NV_MAX * HDIM];
__device__ float g_P[NV_MAX * HDIM];
__device__ float g_Q[NV_MAX * HDIM];
__device__ float g_aggr[NV_MAX * HDIM];
__device__ float g_aggrp[NV_MAX * HDIM];

typedef unsigned long long ull_t;

__device__ __forceinline__ ull_t pack2(float lo, float hi) {
    ull_t r; asm("mov.b64 %0, {%1, %2};" : "=l"(r) : "f"(lo), "f"(hi)); return r;
}
__device__ __forceinline__ void unpack2(ull_t v, float& lo, float& hi) {
    asm("mov.b64 {%0, %1}, %2;" : "=f"(lo), "=f"(hi) : "l"(v));
}
__device__ __forceinline__ ull_t ffma2(ull_t a, ull_t b, ull_t c) {
    ull_t d; asm("fma.rn.f32x2 %0, %1, %2, %3;" : "=l"(d) : "l"(a), "l"(b), "l"(c)); return d;
}
__device__ __forceinline__ float tanh_f(float x) {
    float y; asm("tanh.approx.f32 %0, %1;" : "=f"(y) : "f"(x)); return y;
}
__device__ __forceinline__ float silu_f(float x) {
    return 0.5f * x * (1.0f + tanh_f(0.5f * x));   // single MUFU
}

#define FFMA2_BLOCK(ha, hb, w)                                              \
    {                                                                       \
        ull_t p0 = pack2(ha.x, ha.x), p1 = pack2(ha.y, ha.y);               \
        ull_t p2 = pack2(ha.z, ha.z), p3 = pack2(ha.w, ha.w);               \
        ull_t p4 = pack2(hb.x, hb.x), p5 = pack2(hb.y, hb.y);               \
        ull_t p6 = pack2(hb.z, hb.z), p7 = pack2(hb.w, hb.w);               \
        acc[0][0] = ffma2(p0, w.x, acc[0][0]); acc[0][1] = ffma2(p0, w.y, acc[0][1]); \
        acc[1][0] = ffma2(p1, w.x, acc[1][0]); acc[1][1] = ffma2(p1, w.y, acc[1][1]); \
        acc[2][0] = ffma2(p2, w.x, acc[2][0]); acc[2][1] = ffma2(p2, w.y, acc[2][1]); \
        acc[3][0] = ffma2(p3, w.x, acc[3][0]); acc[3][1] = ffma2(p3, w.y, acc[3][1]); \
        acc[4][0] = ffma2(p4, w.x, acc[4][0]); acc[4][1] = ffma2(p4, w.y, acc[4][1]); \
        acc[5][0] = ffma2(p5, w.x, acc[5][0]); acc[5][1] = ffma2(p5, w.y, acc[5][1]); \
        acc[6][0] = ffma2(p6, w.x, acc[6][0]); acc[6][1] = ffma2(p6, w.y, acc[6][1]); \
        acc[7][0] = ffma2(p7, w.x, acc[7][0]); acc[7][1] = ffma2(p7, w.y, acc[7][1]); \
    }

// 8 rows x 4 cols per thread, rows as two warp-contiguous groups (conflict-free),
// software-pipelined (for 3-CTA kernels; ~80 regs).
template <int K, int ISTRIDE, int WSTRIDE, int HALF>
__device__ __forceinline__ void gemm_8x4(
    const float* __restrict__ inT, const float* __restrict__ W, ull_t acc[8][2])
{
    float4 ha = *(const float4*)(inT);
    float4 hb = *(const float4*)(inT + HALF);
    ulonglong2 w = *(const ulonglong2*)(W);
    #pragma unroll 8
    for (int k = 0; k < K; k++) {
        float4 nha, nhb; ulonglong2 nw;
        if (k + 1 < K) {
            nha = *(const float4*)(inT + (k + 1) * ISTRIDE);
            nhb = *(const float4*)(inT + (k + 1) * ISTRIDE + HALF);
            nw  = *(const ulonglong2*)(W + (k + 1) * WSTRIDE);
        }
        FFMA2_BLOCK(ha, hb, w);
        ha = nha; hb = nhb; w = nw;
    }
}

// No-prefetch variant: fewer live registers (for the 4-CTA edge kernel;
// latency hidden by 32 warps instead of the software pipeline).
template <int K, int ISTRIDE, int WSTRIDE, int HALF>
__device__ __forceinline__ void gemm_8x4_np(
    const float* __restrict__ inT, const float* __restrict__ W, ull_t acc[8][2])
{
    #pragma unroll 8
    for (int k = 0; k < K; k++) {
        float4 ha = *(const float4*)(inT + k * ISTRIDE);
        float4 hb = *(const float4*)(inT + k * ISTRIDE + HALF);
        ulonglong2 w = *(const ulonglong2*)(W + k * WSTRIDE);
        FFMA2_BLOCK(ha, hb, w);
    }
}

__device__ __forceinline__ void zero_acc(ull_t acc[8][2]) {
    #pragma unroll
    for (int i = 0; i < 8; i++) { acc[i][0] = 0ULL; acc[i][1] = 0ULL; }
}

// ============================================================
// Kernel 1 (fused): blockIdx.y==0 -> A,B (+zero aggr); ==1 -> P,Q
//   64 nodes/CTA; 128 out cols.
// ============================================================
__global__ void __launch_bounds__(256, 3) pre_kernel(
    const float* __restrict__ x, const float* __restrict__ pe,
    const float* __restrict__ msg_w1, const float* __restrict__ msg_b1,
    const float* __restrict__ mpos_w1, const float* __restrict__ mpos_b1,
    int N)
{
    extern __shared__ float sm[];
    float* sh_inT = sm;                   // [64][68]
    float* sh_W   = sh_inT + 64 * 68;     // [64][128]
    float* sh_b   = sh_W + 64 * 128;      // [128]

    int tid = threadIdx.x;
    int nb = blockIdx.x * 64;
    int tr = tid & 7, tc = tid >> 3;
    int r0 = 4 * tr, c0 = 4 * tc;

    ull_t acc[8][2];
    zero_acc(acc);
    float* dstA;
    float* dstB;

    if (blockIdx.y == 0) {
        // ---------------- A,B path (msg_w1), K=128 in 2 chunks ----------------
        if (tid < 128) sh_b[tid] = (tid < 64) ? msg_b1[tid] : 0.0f;
        // zero aggregation buffers (edge kernel runs after)
        for (int idx = tid; idx < 2048; idx += 256) {
            int n = idx & 63, s = (idx >> 6) & 15, which = idx >> 10;
            int gn = nb + n;
            if (gn < N) {
                float4* dst = (float4*)((which ? g_aggrp : g_aggr) + (size_t)gn * 64) + s;
                *dst = make_float4(0.f, 0.f, 0.f, 0.f);
            }
        }
        #pragma unroll 1
        for (int ch = 0; ch < 2; ch++) {
            __syncthreads();
            for (int idx = tid; idx < 64 * 128; idx += 256) {
                int k = idx >> 7, c = idx & 127;
                sh_W[idx] = (c < 64) ? msg_w1[(ch * 64 + k) * 64 + c]
                                     : msg_w1[(128 + ch * 64 + k) * 64 + (c - 64)];
            }
            const float* src = (ch == 0) ? x : pe;
            for (int idx = tid; idx < 16 * 64; idx += 256) {
                int n = idx & 63, k4 = idx >> 6;
                int gn = nb + n;
                float4 v = make_float4(0.f, 0.f, 0.f, 0.f);
                if (gn < N) v = *(const float4*)(src + (size_t)gn * 64 + 4 * k4);
                sh_inT[(4 * k4 + 0) * 68 + n] = v.x;
                sh_inT[(4 * k4 + 1) * 68 + n] = v.y;
                sh_inT[(4 * k4 + 2) * 68 + n] = v.z;
                sh_inT[(4 * k4 + 3) * 68 + n] = v.w;
            }
            __syncthreads();
            gemm_8x4<64, 68, 128, 32>(sh_inT + r0, sh_W + c0, acc);
        }
        dstA = g_A; dstB = g_B;
    } else {
        // ---------------- P,Q path (mpos_w1), K=64 ----------------
        if (tid < 128) sh_b[tid] = (tid < 64) ? mpos_b1[tid] : 0.0f;
        for (int idx = tid; idx < 64 * 128; idx += 256) {
            int k = idx >> 7, c = idx & 127;
            sh_W[idx] = (c < 64) ? mpos_w1[k * 64 + c]
                                 : mpos_w1[(64 + k) * 64 + (c - 64)];
        }
        for (int idx = tid; idx < 16 * 64; idx += 256) {
            int n = idx & 63, k4 = idx >> 6;
            int gn = nb + n;
            float4 v = make_float4(0.f, 0.f, 0.f, 0.f);
            if (gn < N) v = *(const float4*)(pe + (size_t)gn * 64 + 4 * k4);
            sh_inT[(4 * k4 + 0) * 68 + n] = v.x;
            sh_inT[(4 * k4 + 1) * 68 + n] = v.y;
            sh_inT[(4 * k4 + 2) * 68 + n] = v.z;
            sh_inT[(4 * k4 + 3) * 68 + n] = v.w;
        }
        __syncthreads();
        gemm_8x4<64, 68, 128, 32>(sh_inT + r0, sh_W + c0, acc);
        dstA = g_P; dstB = g_Q;
    }

    float* dst = (c0 < 64) ? dstA : dstB;
    int lc = c0 & 63;
    float b0 = sh_b[c0], b1 = sh_b[c0 + 1], b2 = sh_b[c0 + 2], b3 = sh_b[c0 + 3];
    #pragma unroll
    for (int i = 0; i < 8; i++) {
        int rr = (i < 4) ? (r0 + i) : (32 + r0 + i - 4);
        int gn = nb + rr;
        if (gn < N) {
            float o0, o1, o2, o3;
            unpack2(acc[i][0], o0, o1);
            unpack2(acc[i][1], o2, o3);
            *(float4*)(dst + (size_t)gn * 64 + lc) =
                make_float4(o0 + b0, o1 + b1, o2 + b2, o3 + b3);
        }
    }
}

// ============================================================
// Kernel 2: edge kernel — 4 CTAs/SM; ONE shared W buffer + ONE tile
// ============================================================
template <bool IS_TANH>
__device__ __forceinline__ void edge_gemm_path(
    const float* hT, const float* W, const float* bias, const int* recs,
    float* __restrict__ aggr, int r0, int c0, int eb, int E)
{
    ull_t acc[8][2];
    zero_acc(acc);
    gemm_8x4_np<64, 132, 64, 64>(hT + r0, W + c0, acc);

    float b0 = bias[c0], b1 = bias[c0 + 1], b2 = bias[c0 + 2], b3 = bias[c0 + 3];
    #pragma unroll
    for (int i = 0; i < 8; i++) {
        int el = (i < 4) ? (r0 + i) : (64 + r0 + i - 4);
        if (eb + el < E) {
            float m0, m1, m2, m3;
            unpack2(acc[i][0], m0, m1);
            unpack2(acc[i][1], m2, m3);
            m0 += b0; m1 += b1; m2 += b2; m3 += b3;
            if (IS_TANH) { m0 = tanh_f(m0); m1 = tanh_f(m1); m2 = tanh_f(m2); m3 = tanh_f(m3); }
            else         { m0 = silu_f(m0); m1 = silu_f(m1); m2 = silu_f(m2); m3 = silu_f(m3); }
            float* dst = aggr + (size_t)recs[el] * 64 + c0;
            asm volatile("red.global.add.v4.f32 [%0], {%1,%2,%3,%4};"
                         :: "l"(dst), "f"(m0), "f"(m1), "f"(m2), "f"(m3) : "memory");
        }
    }
}

__global__ void __launch_bounds__(256, 4) edge_kernel(
    const float* __restrict__ pos,
    const int* __restrict__ ei,          // int32 (JAX demotes int64)
    const float* __restrict__ msg_w1,
    const float* __restrict__ msg_w2, const float* __restrict__ msg_b2,
    const float* __restrict__ mpos_w1,
    const float* __restrict__ mpos_w2, const float* __restrict__ mpos_b2,
    int E)
{
    extern __shared__ float sm[];
    float* sh_t   = sm;                    // [64][132] (both paths)
    float* sh_W   = sh_t + 64 * 132;       // [64][64]  (Wm, then Wp)
    float* sh_we  = sh_W + 64 * 64;        // [64]
    float* sh_ve  = sh_we + 64;
    float* sh_bm  = sh_ve + 64;
    float* sh_bp  = sh_bm + 64;
    int*   sh_rec = (int*)(sh_bp + 64);    // [128]

    int tid = threadIdx.x;
    for (int i = tid; i < 64 * 64; i += 256) sh_W[i] = msg_w2[i];
    if (tid < 64) {
        sh_we[tid] = msg_w1[256 * 64 + tid];   // dist row of msg_w1
        sh_ve[tid] = mpos_w1[128 * 64 + tid];  // dist row of mpos_w1
        sh_bm[tid] = msg_b2[tid];
        sh_bp[tid] = mpos_b2[tid];
    }

    int eb = blockIdx.x * 128;
    int e  = tid & 127;
    int half = tid >> 7;
    int eg = eb + e;
    bool valid = eg < E;
    int snd = 0, rcv = 0;
    if (valid) { snd = ei[eg]; rcv = ei[E + eg]; }
    if (half == 0) sh_rec[e] = rcv;
    float dist = 0.0f;
    if (valid) {
        float dx = pos[snd * 3 + 0] - pos[rcv * 3 + 0];
        float dy = pos[snd * 3 + 1] - pos[rcv * 3 + 1];
        float dz = pos[snd * 3 + 2] - pos[rcv * 3 + 2];
        dist = sqrtf(dx * dx + dy * dy + dz * dz);
    }
    __syncthreads();

    int c0h = half * 32;
    int tr = tid & 15, tc = tid >> 4;
    int r0 = 4 * tr, c0 = 4 * tc;

    // ---- phase A: silu(A[snd]+B[rcv]+dist*we), msg path ----
    {
        const float4* A4 = (const float4*)(g_A + (size_t)snd * 64 + c0h);
        const float4* B4 = (const float4*)(g_B + (size_t)rcv * 64 + c0h);
        const float4* W4 = (const float4*)(sh_we + c0h);
        #pragma unroll
        for (int j = 0; j < 8; j++) {
            float4 a = A4[j], b = B4[j], w = W4[j];
            float* dst = sh_t + (c0h + 4 * j) * 132 + e;
            dst[0]   = silu_f(a.x + b.x + dist * w.x);
            dst[132] = silu_f(a.y + b.y + dist * w.y);
            dst[264] = silu_f(a.z + b.z + dist * w.z);
            dst[396] = silu_f(a.w + b.w + dist * w.w);
        }
    }
    __syncthreads();
    edge_gemm_path<false>(sh_t, sh_W, sh_bm, sh_rec, g_aggr, r0, c0, eb, E);
    __syncthreads();   // GEMM A's reads of sh_t and sh_W complete

    // ---- phase B: load Wp over Wm; tanh(P[snd]+Q[rcv]+dist*ve) tile ----
    for (int i = tid; i < 64 * 64; i += 256) sh_W[i] = mpos_w2[i];
    {
        const float4* P4 = (const float4*)(g_P + (size_t)snd * 64 + c0h);
        const float4* Q4 = (const float4*)(g_Q + (size_t)rcv * 64 + c0h);
        const float4* V4 = (const float4*)(sh_ve + c0h);
        #pragma unroll
        for (int j = 0; j < 8; j++) {
            float4 p = P4[j], q = Q4[j], v = V4[j];
            float* dst = sh_t + (c0h + 4 * j) * 132 + e;
            dst[0]   = tanh_f(p.x + q.x + dist * v.x);
            dst[132] = tanh_f(p.y + q.y + dist * v.y);
            dst[264] = tanh_f(p.z + q.z + dist * v.z);
            dst[396] = tanh_f(p.w + q.w + dist * v.w);
        }
    }
    __syncthreads();
    edge_gemm_path<true>(sh_t, sh_W, sh_bp, sh_rec, g_aggrp, r0, c0, eb, E);
}

// ============================================================
// Kernel 3 (fused): blockIdx.y==0 -> update; ==1 -> update_pe
//   128 nodes/CTA.
// ============================================================
__global__ void __launch_bounds__(256, 3) upd_kernel(
    const float* __restrict__ x, const float* __restrict__ pe,
    const float* __restrict__ upd_w1, const float* __restrict__ upd_b1,
    const float* __restrict__ upd_w2, const float* __restrict__ upd_b2,
    const float* __restrict__ upe_w1, const float* __restrict__ upe_b1,
    const float* __restrict__ upe_w2, const float* __restrict__ upe_b2,
    float* __restrict__ out, int N)
{
    extern __shared__ float sm[];
    float* sh_inT = sm;                    // [64][132] (chunk; reused as hT)
    float* sh_Wc  = sh_inT + 64 * 132;     // [64][64]
    float* sh_b1  = sh_Wc + 64 * 64;       // [64]
    float* sh_b2  = sh_b1 + 64;            // [64]

    bool is_pe = (blockIdx.y != 0);
    const float* w1 = is_pe ? upe_w1 : upd_w1;
    const float* w2 = is_pe ? upe_w2 : upd_w2;
    int nchunks = is_pe ? 2 : 3;

    int tid = threadIdx.x;
    int nb = blockIdx.x * 128;
    if (tid < 64) {
        sh_b1[tid] = is_pe ? upe_b1[tid] : upd_b1[tid];
        sh_b2[tid] = is_pe ? upe_b2[tid] : upd_b2[tid];
    }

    int tr = tid & 15, tc = tid >> 4;
    int r0 = 4 * tr, c0 = 4 * tc;

    ull_t acc[8][2];
    zero_acc(acc);

    #pragma unroll 1
    for (int ch = 0; ch < nchunks; ch++) {
        __syncthreads();
        for (int idx = tid; idx < 64 * 64; idx += 256)
            sh_Wc[idx] = w1[ch * 64 * 64 + idx];
        const float* src = is_pe ? ((ch == 0) ? pe : g_aggrp)
                                 : ((ch == 0) ? x : (ch == 1) ? pe : g_aggr);
        for (int idx = tid; idx < 16 * 128; idx += 256) {
            int n = idx & 127, k4 = idx >> 7;
            int gn = nb + n;
            float4 v = make_float4(0.f, 0.f, 0.f, 0.f);
            if (gn < N) v = *(const float4*)(src + (size_t)gn * 64 + 4 * k4);
            sh_inT[(4 * k4 + 0) * 132 + n] = v.x;
            sh_inT[(4 * k4 + 1) * 132 + n] = v.y;
            sh_inT[(4 * k4 + 2) * 132 + n] = v.z;
            sh_inT[(4 * k4 + 3) * 132 + n] = v.w;
        }
        __syncthreads();
        gemm_8x4<64, 132, 64, 64>(sh_inT + r0, sh_Wc + c0, acc);
    }

    __syncthreads();   // all reads of inT done before overwrite as hT
    #pragma unroll
    for (int j = 0; j < 2; j++) {
        float bj0 = sh_b1[c0 + 2 * j], bj1 = sh_b1[c0 + 2 * j + 1];
        float lo[8], hi[8];
        #pragma unroll
        for (int i = 0; i < 8; i++) { unpack2(acc[i][j], lo[i], hi[i]); }
        #pragma unroll
        for (int i = 0; i < 8; i++) {
            lo[i] = is_pe ? tanh_f(lo[i] + bj0) : silu_f(lo[i] + bj0);
            hi[i] = is_pe ? tanh_f(hi[i] + bj1) : silu_f(hi[i] + bj1);
        }
        float* d0 = sh_inT + (c0 + 2 * j) * 132;
        float* d1 = d0 + 132;
        *(float4*)(d0 + r0)      = make_float4(lo[0], lo[1], lo[2], lo[3]);
        *(float4*)(d0 + 64 + r0) = make_float4(lo[4], lo[5], lo[6], lo[7]);
        *(float4*)(d1 + r0)      = make_float4(hi[0], hi[1], hi[2], hi[3]);
        *(float4*)(d1 + 64 + r0) = make_float4(hi[4], hi[5], hi[6], hi[7]);
    }
    for (int idx = tid; idx < 64 * 64; idx += 256) sh_Wc[idx] = w2[idx];
    __syncthreads();

    ull_t a2[8][2];
    zero_acc(a2);
    gemm_8x4<64, 132, 64, 64>(sh_inT + r0, sh_Wc + c0, a2);

    float b0 = sh_b2[c0], b1 = sh_b2[c0 + 1], b2 = sh_b2[c0 + 2], b3 = sh_b2[c0 + 3];
    float* obase = out + (is_pe ? (size_t)N * 64 : 0);
    #pragma unroll
    for (int i = 0; i < 8; i++) {
        int rr = (i < 4) ? (r0 + i) : (64 + r0 + i - 4);
        int g = nb + rr;
        if (g < N) {
            float o0, o1, o2, o3;
            unpack2(a2[i][0], o0, o1);
            unpack2(a2[i][1], o2, o3);
            if (is_pe) { o0 = tanh_f(o0 + b0); o1 = tanh_f(o1 + b1);
                         o2 = tanh_f(o2 + b2); o3 = tanh_f(o3 + b3); }
            else       { o0 += b0; o1 += b1; o2 += b2; o3 += b3; }
            *(float4*)(obase + (size_t)g * 64 + c0) = make_float4(o0, o1, o2, o3);
        }
    }
}

// ============================================================
// Host launch
// ============================================================
extern "C" void kernel_launch(void* const* d_in, const int* in_sizes, int n_in,
                              void* d_out, int out_size)
{
    const float* x       = (const float*)d_in[0];
    const float* pos     = (const float*)d_in[1];
    const float* pe      = (const float*)d_in[2];
    const int*   ei      = (const int*)d_in[3];
    const float* msg_w1  = (const float*)d_in[4];
    const float* msg_b1  = (const float*)d_in[5];
    const float* msg_w2  = (const float*)d_in[6];
    const float* msg_b2  = (const float*)d_in[7];
    const float* mpos_w1 = (const float*)d_in[8];
    const float* mpos_b1 = (const float*)d_in[9];
    const float* mpos_w2 = (const float*)d_in[10];
    const float* mpos_b2 = (const float*)d_in[11];
    const float* upd_w1  = (const float*)d_in[12];
    const float* upd_b1  = (const float*)d_in[13];
    const float* upd_w2  = (const float*)d_in[14];
    const float* upd_b2  = (const float*)d_in[15];
    const float* upe_w1  = (const float*)d_in[16];
    const float* upe_b1  = (const float*)d_in[17];
    const float* upe_w2  = (const float*)d_in[18];
    const float* upe_b2  = (const float*)d_in[19];

    int N = in_sizes[0] / 64;
    int E = in_sizes[3] / 2;

    const int SMEM_PRE  = (64 * 68 + 64 * 128 + 128) * 4;            // 50,688 B
    const int SMEM_EDGE = (64 * 132 + 64 * 64 + 256) * 4 + 512;      // 51,712 B
    const int SMEM_UPD  = (64 * 132 + 64 * 64 + 128) * 4;            // 50,688 B

    cudaFuncSetAttribute(pre_kernel,  cudaFuncAttributeMaxDynamicSharedMemorySize, SMEM_PRE);
    cudaFuncSetAttribute(edge_kernel, cudaFuncAttributeMaxDynamicSharedMemorySize, SMEM_EDGE);
    cudaFuncSetAttribute(upd_kernel,  cudaFuncAttributeMaxDynamicSharedMemorySize, SMEM_UPD);

    dim3 gpre((N + 63) / 64, 2);
    dim3 gupd((N + 127) / 128, 2);
    pre_kernel<<<gpre, 256, SMEM_PRE>>>(x, pe, msg_w1, msg_b1, mpos_w1, mpos_b1, N);
    edge_kernel<<<(E + 127) / 128, 256, SMEM_EDGE>>>(pos, ei, msg_w1, msg_w2, msg_b2,
                                                     mpos_w1, mpos_w2, mpos_b2, E);
    upd_kernel<<<gupd, 256, SMEM_UPD>>>(x, pe, upd_w1, upd_b1, upd_w2, upd_b2,
                                        upe_w1, upe_b1, upe_w2, upe_b2,
                                        (float*)d_out, N);
}